// round 3
// baseline (speedup 1.0000x reference)
#include <cuda_runtime.h>
#include <cuda_bf16.h>
#include <cstdint>

#define SEQL  256
#define BATCHN 64
#define EMBD  256
#define HID   512
#define OUTD  18
#define MROWS (SEQL*BATCHN)   // 16384

typedef unsigned long long u64;

// ---------------- packed f32x2 helpers ----------------
__device__ __forceinline__ u64 ffma2(u64 a, u64 b, u64 c) {
    u64 d; asm("fma.rn.f32x2 %0, %1, %2, %3;" : "=l"(d) : "l"(a), "l"(b), "l"(c));
    return d;
}
__device__ __forceinline__ u64 pack2(float lo, float hi) {
    u64 r; asm("mov.b64 %0, {%1, %2};" : "=l"(r) : "f"(lo), "f"(hi));
    return r;
}
__device__ __forceinline__ float2 unpk2(u64 v) {
    float lo, hi; asm("mov.b64 {%0, %1}, %2;" : "=f"(lo), "=f"(hi) : "l"(v));
    return make_float2(lo, hi);
}

// ---------------- scratch (static device arrays; no allocation) ----------------
__device__ float g_post_emb[MROWS * EMBD];            // 16 MB
__device__ float g_xp0[2 * SEQL * BATCHN * HID];      // 64 MB  [d][s][b][h]
__device__ float g_h0 [MROWS * 2 * HID];              // 64 MB  [s][b][2H]
__device__ float g_xp1[2 * SEQL * BATCHN * HID];      // 64 MB
__device__ float g_h1 [MROWS * 2 * HID];              // 64 MB
__device__ float g_hsc[2][2][BATCHN][HID];            // 512 KB [buf][dir][b][h]

// =====================================================================
// fp32 SIMT GEMM with packed f32x2 FMA: C[M,N] = A[M,K] * Bw[N,K]^T + bias
// BM=128, BN=64, BK=16, 256 threads, thread tile 8x4, double buffered.
// =====================================================================
template<int GATHER, int SCATTER, int NBIAS>
__global__ void __launch_bounds__(256, 2)
gemm_k(const float* __restrict__ A, const float* __restrict__ Bw,
       const float* __restrict__ bias1, const float* __restrict__ bias2,
       float* __restrict__ C,
       const int* __restrict__ gidx, const float* __restrict__ gtab,
       int N, int K)
{
    constexpr int BM = 128, BN = 64, BK = 16;
    __shared__ float As[2][BK][BM];
    __shared__ float Bs[2][BK][BN];

    const int tid   = threadIdx.x;
    const int mBase = blockIdx.y * BM;
    const int nBase = blockIdx.x * BN;
    const int tx = tid & 15;      // n-frag (4 cols)
    const int ty = tid >> 4;      // m-frag (8 rows)

    const int ar0 = tid >> 2;             // 0..63  (rows ar0 and ar0+64)
    const int ak4 = (tid & 3) * 4;        // k offset within BK
    const int br  = tid >> 2;             // 0..63

    const int row0 = mBase + ar0;
    const int row1 = row0 + 64;
    const float* arp0;
    const float* arp1;
    if (GATHER) {
        arp0 = gtab + (size_t)gidx[row0] * K;
        arp1 = gtab + (size_t)gidx[row1] * K;
    } else {
        arp0 = A + (size_t)row0 * K;
        arp1 = A + (size_t)row1 * K;
    }
    const int   brow = nBase + br;
    const float* brp = (brow < N) ? (Bw + (size_t)brow * K) : nullptr;

    const int KT = K / BK;

    float4 a0r, a1r, b0r;

    // prologue: stage 0
    a0r = *reinterpret_cast<const float4*>(arp0 + ak4);
    a1r = *reinterpret_cast<const float4*>(arp1 + ak4);
    b0r = brp ? *reinterpret_cast<const float4*>(brp + ak4) : make_float4(0.f,0.f,0.f,0.f);
    {
        As[0][ak4+0][ar0]    = a0r.x; As[0][ak4+1][ar0]    = a0r.y;
        As[0][ak4+2][ar0]    = a0r.z; As[0][ak4+3][ar0]    = a0r.w;
        As[0][ak4+0][ar0+64] = a1r.x; As[0][ak4+1][ar0+64] = a1r.y;
        As[0][ak4+2][ar0+64] = a1r.z; As[0][ak4+3][ar0+64] = a1r.w;
        Bs[0][ak4+0][br] = b0r.x; Bs[0][ak4+1][br] = b0r.y;
        Bs[0][ak4+2][br] = b0r.z; Bs[0][ak4+3][br] = b0r.w;
    }
    __syncthreads();

    // acc2[i2][j]: packed pair of rows (ty*8 + 2*i2, +1) x col (tx*4 + j)
    u64 acc2[4][4];
    #pragma unroll
    for (int i = 0; i < 4; i++)
        #pragma unroll
        for (int j = 0; j < 4; j++) acc2[i][j] = 0ull;   // bits of (0.f, 0.f)

    #pragma unroll 1
    for (int kt = 0; kt < KT; kt++) {
        const int buf = kt & 1;
        if (kt + 1 < KT) {
            const int ko = (kt + 1) * BK + ak4;
            a0r = *reinterpret_cast<const float4*>(arp0 + ko);
            a1r = *reinterpret_cast<const float4*>(arp1 + ko);
            b0r = brp ? *reinterpret_cast<const float4*>(brp + ko) : make_float4(0.f,0.f,0.f,0.f);
        }
        #pragma unroll
        for (int k = 0; k < BK; k++) {
            // A fragment: 8 consecutive floats = 4 packed f32x2 pairs, read raw
            ulonglong2 aA = *reinterpret_cast<const ulonglong2*>(&As[buf][k][ty * 8]);
            ulonglong2 aB = *reinterpret_cast<const ulonglong2*>(&As[buf][k][ty * 8 + 4]);
            float4 bf = *reinterpret_cast<const float4*>(&Bs[buf][k][tx * 4]);
            u64 a2[4] = {aA.x, aA.y, aB.x, aB.y};
            u64 b2[4] = {pack2(bf.x, bf.x), pack2(bf.y, bf.y),
                         pack2(bf.z, bf.z), pack2(bf.w, bf.w)};
            #pragma unroll
            for (int i = 0; i < 4; i++)
                #pragma unroll
                for (int j = 0; j < 4; j++)
                    acc2[i][j] = ffma2(a2[i], b2[j], acc2[i][j]);
        }
        if (kt + 1 < KT) {
            const int nb = (kt + 1) & 1;
            As[nb][ak4+0][ar0]    = a0r.x; As[nb][ak4+1][ar0]    = a0r.y;
            As[nb][ak4+2][ar0]    = a0r.z; As[nb][ak4+3][ar0]    = a0r.w;
            As[nb][ak4+0][ar0+64] = a1r.x; As[nb][ak4+1][ar0+64] = a1r.y;
            As[nb][ak4+2][ar0+64] = a1r.z; As[nb][ak4+3][ar0+64] = a1r.w;
            Bs[nb][ak4+0][br] = b0r.x; Bs[nb][ak4+1][br] = b0r.y;
            Bs[nb][ak4+2][br] = b0r.z; Bs[nb][ak4+3][br] = b0r.w;
            __syncthreads();
        }
    }

    // epilogue
    #pragma unroll
    for (int i2 = 0; i2 < 4; i2++) {
        #pragma unroll
        for (int j = 0; j < 4; j++) {
            const int n = nBase + tx * 4 + j;
            if (n >= N) continue;
            float2 v2 = unpk2(acc2[i2][j]);
            float bsum = 0.f;
            if (NBIAS >= 1) bsum += bias1[n];
            if (NBIAS >= 2) bsum += bias2[n];
            #pragma unroll
            for (int half = 0; half < 2; half++) {
                const int m = mBase + ty * 8 + i2 * 2 + half;
                float v = (half ? v2.y : v2.x) + bsum;
                if (SCATTER) {
                    const int s = m >> 6, b = m & 63, d = n >> 9, h = n & 511;
                    C[(size_t)d * (SEQL * BATCHN * HID) +
                      (size_t)s * (BATCHN * HID) + b * HID + h] = v;
                } else {
                    C[(size_t)m * N + n] = v;
                }
            }
        }
    }
}

// =====================================================================
// Recurrence kernel: 16 clusters of 8 CTAs (128 CTAs total).
// cluster = (dir d, batch-octet g); CTA rank r = 64-output slice.
// W_hh slice [64,512] lives in registers as 64 packed f32x2 pairs/thread.
// h exchanged via L2 (stcg/ldcg) + barrier.cluster per step.
// =====================================================================
__global__ void __cluster_dims__(8, 1, 1) __launch_bounds__(256, 1)
rnn_k(const float* __restrict__ xp,      // [2][SEQL][BATCHN][HID]
      const float* __restrict__ whh,     // [2][HID][HID]
      float* __restrict__ hout)          // [SEQL][BATCHN][2*HID]
{
    const int r   = blockIdx.x & 7;
    const int cid = blockIdx.x >> 3;
    const int d   = cid & 1;
    const int g   = cid >> 1;            // batch octet: batches g*8 .. g*8+7
    const int t   = threadIdx.x;
    const int c   = t >> 6;              // k-chunk 0..3
    const int oo  = t & 63;
    const int orow = r * 64 + oo;
    const int c128 = c * 128;

    // --- load W slice as 64 packed pairs (k-even, k-odd) ---
    u64 Wp[64];
    const float* wrow = whh + ((size_t)(d * HID + orow)) * HID + c128;
    #pragma unroll
    for (int i = 0; i < 32; i++) {
        ulonglong2 v = *reinterpret_cast<const ulonglong2*>(wrow + i * 4);
        Wp[2 * i]     = v.x;
        Wp[2 * i + 1] = v.y;
    }

    // --- zero scratch buf 0 for our (d, batch-octet) slice ---
    float* sc0 = &g_hsc[0][d][g * 8][0];
    #pragma unroll
    for (int i = t * 4; i < 4096; i += 1024)
        *reinterpret_cast<float4*>(sc0 + i) = make_float4(0.f, 0.f, 0.f, 0.f);

    asm volatile("barrier.cluster.arrive.aligned;" ::: "memory");
    asm volatile("barrier.cluster.wait.aligned;"   ::: "memory");

    __shared__ float h_sm[8][HID];
    __shared__ float part[4][64][9];     // pad to 9: conflict-free

    #pragma unroll 1
    for (int step = 0; step < SEQL; step++) {
        const int s = d ? (SEQL - 1 - step) : step;

        // load h_prev [8][512] from L2 scratch into smem
        const float* src = &g_hsc[step & 1][d][g * 8][0];
        #pragma unroll
        for (int i = t * 4; i < 4096; i += 1024) {
            float4 v = __ldcg(reinterpret_cast<const float4*>(src + i));
            *reinterpret_cast<float4*>(&h_sm[0][0] + i) = v;
        }
        __syncthreads();

        // partial dot products with packed f32x2 FMA:
        // lanes accumulate (even-k, odd-k) partial sums
        u64 acc2[8] = {0ull,0ull,0ull,0ull,0ull,0ull,0ull,0ull};
        #pragma unroll
        for (int i = 0; i < 32; i++) {
            const u64 w0 = Wp[2 * i], w1 = Wp[2 * i + 1];
            #pragma unroll
            for (int b = 0; b < 8; b++) {
                ulonglong2 hv = *reinterpret_cast<const ulonglong2*>(&h_sm[b][c128 + 4 * i]);
                acc2[b] = ffma2(w0, hv.x, acc2[b]);
                acc2[b] = ffma2(w1, hv.y, acc2[b]);
            }
        }
        #pragma unroll
        for (int b = 0; b < 8; b++) {
            float2 f = unpk2(acc2[b]);
            part[c][oo][b] = f.x + f.y;
        }
        __syncthreads();

        // reduce over 4 k-chunks; each thread finalizes 2 of the 512 outputs
        const float* xpb = xp + ((size_t)(d * SEQL + s) * BATCHN) * HID;
        float* scn = &g_hsc[(step + 1) & 1][d][0][0];
        #pragma unroll
        for (int half = 0; half < 2; half++) {
            const int b = (t >> 6) + half * 4;
            float v = part[0][oo][b] + part[1][oo][b] + part[2][oo][b] + part[3][oo][b];
            v += xpb[(size_t)(g * 8 + b) * HID + orow];
            v = fmaxf(v, 0.f);
            __stcg(&scn[(size_t)(g * 8 + b) * HID + orow], v);
            hout[((size_t)s * BATCHN + g * 8 + b) * (2 * HID) + d * HID + orow] = v;
        }

        asm volatile("barrier.cluster.arrive.aligned;" ::: "memory");
        asm volatile("barrier.cluster.wait.aligned;"   ::: "memory");
    }
}

// =====================================================================
extern "C" void kernel_launch(void* const* d_in, const int* in_sizes, int n_in,
                              void* d_out, int out_size)
{
    const int*   text   = (const int*)  d_in[0];
    const float* emb    = (const float*)d_in[1];
    const float* emfc_w = (const float*)d_in[2];
    const float* emfc_b = (const float*)d_in[3];
    const float* w_ih0  = (const float*)d_in[4];
    const float* w_hh0  = (const float*)d_in[5];
    const float* b_ih0  = (const float*)d_in[6];
    const float* b_hh0  = (const float*)d_in[7];
    const float* w_ih1  = (const float*)d_in[8];
    const float* w_hh1  = (const float*)d_in[9];
    const float* b_ih1  = (const float*)d_in[10];
    const float* b_hh1  = (const float*)d_in[11];
    const float* fc_w   = (const float*)d_in[12];
    const float* fc_b   = (const float*)d_in[13];
    float* out = (float*)d_out;

    float *p_pe, *p_xp0, *p_h0, *p_xp1, *p_h1;
    cudaGetSymbolAddress((void**)&p_pe,  g_post_emb);
    cudaGetSymbolAddress((void**)&p_xp0, g_xp0);
    cudaGetSymbolAddress((void**)&p_h0,  g_h0);
    cudaGetSymbolAddress((void**)&p_xp1, g_xp1);
    cudaGetSymbolAddress((void**)&p_h1,  g_h1);

    dim3 blk(256);

    // 1) post_emb = gather(emb_table, text) @ emfc_w^T + emfc_b        [16384,256]
    gemm_k<1,0,1><<<dim3(EMBD/64, MROWS/128), blk>>>(
        nullptr, emfc_w, emfc_b, nullptr, p_pe, text, emb, EMBD, EMBD);

    // 2) xp0[d][s][b][h] = post_emb @ w_ih0^T + (b_ih0+b_hh0)          N=1024,K=256
    gemm_k<0,1,2><<<dim3(1024/64, MROWS/128), blk>>>(
        p_pe, w_ih0, b_ih0, b_hh0, p_xp0, nullptr, nullptr, 1024, EMBD);

    // 3) layer-0 bidirectional recurrence -> h0 [s][b][1024]
    rnn_k<<<128, blk>>>(p_xp0, w_hh0, p_h0);

    // 4) xp1 = h0 @ w_ih1^T + (b_ih1+b_hh1)                            N=1024,K=1024
    gemm_k<0,1,2><<<dim3(1024/64, MROWS/128), blk>>>(
        p_h0, w_ih1, b_ih1, b_hh1, p_xp1, nullptr, nullptr, 1024, 1024);

    // 5) layer-1 recurrence -> h1
    rnn_k<<<128, blk>>>(p_xp1, w_hh1, p_h1);

    // 6) out = h1 @ fc_w^T + fc_b                                      N=18,K=1024
    gemm_k<0,0,1><<<dim3(1, MROWS/128), blk>>>(
        p_h1, fc_w, fc_b, nullptr, out, nullptr, nullptr, OUTD, 1024);
}

// round 5
// speedup vs baseline: 1.1907x; 1.1907x over previous
#include <cuda_runtime.h>
#include <cuda_bf16.h>
#include <cstdint>

#define SEQL  256
#define BATCHN 64
#define EMBD  256
#define HID   512
#define OUTD  18
#define MROWS (SEQL*BATCHN)   // 16384

typedef unsigned long long u64;

// ---------------- packed f32x2 helpers ----------------
__device__ __forceinline__ u64 ffma2(u64 a, u64 b, u64 c) {
    u64 d; asm("fma.rn.f32x2 %0, %1, %2, %3;" : "=l"(d) : "l"(a), "l"(b), "l"(c));
    return d;
}
__device__ __forceinline__ u64 pack2(float lo, float hi) {
    u64 r; asm("mov.b64 %0, {%1, %2};" : "=l"(r) : "f"(lo), "f"(hi));
    return r;
}
__device__ __forceinline__ float2 unpk2(u64 v) {
    float lo, hi; asm("mov.b64 {%0, %1}, %2;" : "=f"(lo), "=f"(hi) : "l"(v));
    return make_float2(lo, hi);
}

// ---------------- scratch (static device arrays; no allocation) ----------------
__device__ float g_post_emb[MROWS * EMBD];            // 16 MB
__device__ float g_xp0[2 * SEQL * BATCHN * HID];      // 64 MB  [d][s][b][h]
__device__ float g_h0 [MROWS * 2 * HID];              // 64 MB  [s][b][2H]
__device__ float g_xp1[2 * SEQL * BATCHN * HID];      // 64 MB
__device__ float g_h1 [MROWS * 2 * HID];              // 64 MB
__device__ float g_hsc[2][2][BATCHN][HID];            // 512 KB [buf][dir][b][h]

// =====================================================================
// fp32 SIMT GEMM, f32x2 FMA: C[M,N] = A[M,K] * Bw[N,K]^T + bias
// BM=128, BN=64 or 128, BK=16, 256 threads, thread tile 8x(BN/16),
// double buffered. Bw is pre-offset by caller; nOff gives the global
// column offset for bias / scatter / output indexing.
// =====================================================================
template<int GATHER, int SCATTER, int NBIAS, int BN>
__global__ void __launch_bounds__(256, 2)
gemm_k(const float* __restrict__ A, const float* __restrict__ Bw,
       const float* __restrict__ bias1, const float* __restrict__ bias2,
       float* __restrict__ C,
       const int* __restrict__ gidx, const float* __restrict__ gtab,
       int N, int K, int nOff, int Nfull)
{
    constexpr int BM = 128, BK = 16;
    constexpr int COLS = BN / 16;              // 4 or 8 cols per thread
    constexpr int BF4  = BN / 64;              // float4s per thread per B stage
    __shared__ float As[2][BK][BM];
    __shared__ float Bs[2][BK][BN];

    const int tid   = threadIdx.x;
    const int mBase = blockIdx.y * BM;
    const int nBase = blockIdx.x * BN;
    const int tx = tid & 15;                   // col group
    const int ty = tid >> 4;                   // row group (8 rows)

    // A-stage mapping
    const int ar0 = tid >> 2;                  // rows ar0, ar0+64
    const int ak4 = (tid & 3) * 4;
    // B-stage mapping (local row br within the BN slab)
    const int br  = (BN == 128) ? (tid >> 1) : (tid >> 2);
    const int bko = (BN == 128) ? ((tid & 1) * 8) : ((tid & 3) * 4);

    const int row0 = mBase + ar0;
    const int row1 = row0 + 64;
    const float* arp0;
    const float* arp1;
    if (GATHER) {
        arp0 = gtab + (size_t)gidx[row0] * K;
        arp1 = gtab + (size_t)gidx[row1] * K;
    } else {
        arp0 = A + (size_t)row0 * K;
        arp1 = A + (size_t)row1 * K;
    }
    const int brow = nBase + br;               // global B row (FIX: include nBase)
    const float* brp = (brow < N) ? (Bw + (size_t)brow * K) : nullptr;

    const int KT = K / BK;

    float4 a0r, a1r, b0r[BF4];

    // prologue: stage 0
    a0r = *reinterpret_cast<const float4*>(arp0 + ak4);
    a1r = *reinterpret_cast<const float4*>(arp1 + ak4);
    #pragma unroll
    for (int f = 0; f < BF4; f++)
        b0r[f] = brp ? *reinterpret_cast<const float4*>(brp + bko + 4 * f)
                     : make_float4(0.f, 0.f, 0.f, 0.f);
    {
        As[0][ak4+0][ar0]    = a0r.x; As[0][ak4+1][ar0]    = a0r.y;
        As[0][ak4+2][ar0]    = a0r.z; As[0][ak4+3][ar0]    = a0r.w;
        As[0][ak4+0][ar0+64] = a1r.x; As[0][ak4+1][ar0+64] = a1r.y;
        As[0][ak4+2][ar0+64] = a1r.z; As[0][ak4+3][ar0+64] = a1r.w;
        #pragma unroll
        for (int f = 0; f < BF4; f++) {
            Bs[0][bko+4*f+0][br] = b0r[f].x; Bs[0][bko+4*f+1][br] = b0r[f].y;
            Bs[0][bko+4*f+2][br] = b0r[f].z; Bs[0][bko+4*f+3][br] = b0r[f].w;
        }
    }
    __syncthreads();

    u64 acc2[4][COLS];
    #pragma unroll
    for (int i = 0; i < 4; i++)
        #pragma unroll
        for (int j = 0; j < COLS; j++) acc2[i][j] = 0ull;

    #pragma unroll 1
    for (int kt = 0; kt < KT; kt++) {
        const int buf = kt & 1;
        if (kt + 1 < KT) {
            const int ka = (kt + 1) * BK;
            a0r = *reinterpret_cast<const float4*>(arp0 + ka + ak4);
            a1r = *reinterpret_cast<const float4*>(arp1 + ka + ak4);
            #pragma unroll
            for (int f = 0; f < BF4; f++)
                b0r[f] = brp ? *reinterpret_cast<const float4*>(brp + ka + bko + 4 * f)
                             : make_float4(0.f, 0.f, 0.f, 0.f);
        }
        #pragma unroll
        for (int k = 0; k < BK; k++) {
            ulonglong2 aA = *reinterpret_cast<const ulonglong2*>(&As[buf][k][ty * 8]);
            ulonglong2 aB = *reinterpret_cast<const ulonglong2*>(&As[buf][k][ty * 8 + 4]);
            u64 a2[4] = {aA.x, aA.y, aB.x, aB.y};
            u64 b2[COLS];
            #pragma unroll
            for (int f = 0; f < BF4; f++) {
                float4 bf = *reinterpret_cast<const float4*>(&Bs[buf][k][tx * COLS + 4 * f]);
                b2[4*f+0] = pack2(bf.x, bf.x); b2[4*f+1] = pack2(bf.y, bf.y);
                b2[4*f+2] = pack2(bf.z, bf.z); b2[4*f+3] = pack2(bf.w, bf.w);
            }
            #pragma unroll
            for (int i = 0; i < 4; i++)
                #pragma unroll
                for (int j = 0; j < COLS; j++)
                    acc2[i][j] = ffma2(a2[i], b2[j], acc2[i][j]);
        }
        if (kt + 1 < KT) {
            const int nb = (kt + 1) & 1;
            As[nb][ak4+0][ar0]    = a0r.x; As[nb][ak4+1][ar0]    = a0r.y;
            As[nb][ak4+2][ar0]    = a0r.z; As[nb][ak4+3][ar0]    = a0r.w;
            As[nb][ak4+0][ar0+64] = a1r.x; As[nb][ak4+1][ar0+64] = a1r.y;
            As[nb][ak4+2][ar0+64] = a1r.z; As[nb][ak4+3][ar0+64] = a1r.w;
            #pragma unroll
            for (int f = 0; f < BF4; f++) {
                Bs[nb][bko+4*f+0][br] = b0r[f].x; Bs[nb][bko+4*f+1][br] = b0r[f].y;
                Bs[nb][bko+4*f+2][br] = b0r[f].z; Bs[nb][bko+4*f+3][br] = b0r[f].w;
            }
            __syncthreads();
        }
    }

    // epilogue
    #pragma unroll
    for (int i2 = 0; i2 < 4; i2++) {
        #pragma unroll
        for (int j = 0; j < COLS; j++) {
            const int n = tx * COLS + j;           // local col
            if (nBase + n >= N) continue;
            const int nglob = nBase + n + nOff;    // global col
            float2 v2 = unpk2(acc2[i2][j]);
            float bsum = 0.f;
            if (NBIAS >= 1) bsum += bias1[nglob];
            if (NBIAS >= 2) bsum += bias2[nglob];
            #pragma unroll
            for (int half = 0; half < 2; half++) {
                const int m = mBase + ty * 8 + i2 * 2 + half;
                float v = (half ? v2.y : v2.x) + bsum;
                if (SCATTER) {
                    const int s = m >> 6, b = m & 63, d = nglob >> 9, h = nglob & 511;
                    C[(size_t)d * (SEQL * BATCHN * HID) +
                      (size_t)s * (BATCHN * HID) + b * HID + h] = v;
                } else {
                    C[(size_t)m * Nfull + nglob] = v;
                }
            }
        }
    }
}

// =====================================================================
// Recurrence: 16 clusters of 8 CTAs. cluster = (dir d, batch-octet g);
// CTA rank r = 64-output slice. Thread = (warp w = k-chunk of 64, oo):
// computes 2 orows (oo, oo+32) x 8 batches over its 64-k chunk.
// W_hh slice in registers (2x64 floats = 64 u64 / thread).
// h staged warp-locally (warp w only touches k [64w,64w+64)).
// hout stores + next-step xp prefetch hidden in the arrive->wait window.
// =====================================================================
__global__ void __cluster_dims__(8, 1, 1) __launch_bounds__(256, 1)
rnn_k(const float* __restrict__ xp,      // [2][SEQL][BATCHN][HID]
      const float* __restrict__ whh,     // [2][HID][HID]
      float* __restrict__ hout)          // [SEQL][BATCHN][2*HID]
{
    const int r   = blockIdx.x & 7;
    const int cid = blockIdx.x >> 3;
    const int d   = cid & 1;
    const int g   = cid >> 1;
    const int t   = threadIdx.x;
    const int w   = t >> 5;              // warp index = k-chunk 0..7
    const int oo  = t & 31;
    const int o0  = r * 64 + oo;
    const int o1  = o0 + 32;
    const int ck  = w * 64;

    // --- W slices into registers as (even-k, odd-k) pairs ---
    u64 Wp0[32], Wp1[32];
    {
        const float* w0 = whh + (size_t)(d * HID + o0) * HID + ck;
        const float* w1 = whh + (size_t)(d * HID + o1) * HID + ck;
        #pragma unroll
        for (int i = 0; i < 16; i++) {
            ulonglong2 v0 = *reinterpret_cast<const ulonglong2*>(w0 + 4 * i);
            Wp0[2 * i] = v0.x; Wp0[2 * i + 1] = v0.y;
            ulonglong2 v1 = *reinterpret_cast<const ulonglong2*>(w1 + 4 * i);
            Wp1[2 * i] = v1.x; Wp1[2 * i + 1] = v1.y;
        }
    }

    // --- zero scratch buf 0 for our (d, batch-octet) slice ---
    float* sc0 = &g_hsc[0][d][g * 8][0];
    for (int i = t * 4; i < 4096; i += 1024)
        *reinterpret_cast<float4*>(sc0 + i) = make_float4(0.f, 0.f, 0.f, 0.f);

    asm volatile("barrier.cluster.arrive.aligned;" ::: "memory");
    asm volatile("barrier.cluster.wait.aligned;"   ::: "memory");

    __shared__ float h_sm[8][HID];       // 16 KB
    __shared__ float part[8][64][12];    // 24 KB, 48B rows (16B-aligned, low conflict)

    // reduce-phase mapping: thread handles outputs (ol, b0) and (ol, b0+1)
    const int ol  = t >> 2;              // 0..63
    const int b0  = (t & 3) * 2;         // 0,2,4,6
    const int orF = r * 64 + ol;
    const int gb0 = g * 8 + b0;

    float xv0, xv1;
    {
        const int s0 = d ? (SEQL - 1) : 0;
        const float* xpb = xp + ((size_t)(d * SEQL + s0) * BATCHN) * HID;
        xv0 = xpb[(size_t)gb0 * HID + orF];
        xv1 = xpb[(size_t)(gb0 + 1) * HID + orF];
    }

    #pragma unroll 1
    for (int step = 0; step < SEQL; step++) {
        const int s = d ? (SEQL - 1 - step) : step;

        // warp-local h staging: warp w loads h[0..7][ck..ck+63]
        {
            const float* base = &g_hsc[step & 1][d][g * 8][0];
            #pragma unroll
            for (int j = 0; j < 4; j++) {
                const int flat = j * 32 + oo;           // 0..127
                const int b  = flat >> 4;
                const int kk = (flat & 15) * 4;
                float4 v = __ldcg(reinterpret_cast<const float4*>(
                                  base + (size_t)b * HID + ck + kk));
                *reinterpret_cast<float4*>(&h_sm[b][ck + kk]) = v;
            }
        }
        __syncwarp();

        u64 a0[8], a1[8];
        #pragma unroll
        for (int b = 0; b < 8; b++) { a0[b] = 0ull; a1[b] = 0ull; }
        #pragma unroll
        for (int i = 0; i < 16; i++) {
            #pragma unroll
            for (int b = 0; b < 8; b++) {
                ulonglong2 hv = *reinterpret_cast<const ulonglong2*>(&h_sm[b][ck + 4 * i]);
                a0[b] = ffma2(Wp0[2 * i],     hv.x, a0[b]);
                a0[b] = ffma2(Wp0[2 * i + 1], hv.y, a0[b]);
                a1[b] = ffma2(Wp1[2 * i],     hv.x, a1[b]);
                a1[b] = ffma2(Wp1[2 * i + 1], hv.y, a1[b]);
            }
        }
        // fold pair-lanes, store partials (4x STS.128)
        {
            float p[8], q[8];
            #pragma unroll
            for (int b = 0; b < 8; b++) {
                float2 f0 = unpk2(a0[b]); p[b] = f0.x + f0.y;
                float2 f1 = unpk2(a1[b]); q[b] = f1.x + f1.y;
            }
            *reinterpret_cast<float4*>(&part[w][oo][0])      = make_float4(p[0], p[1], p[2], p[3]);
            *reinterpret_cast<float4*>(&part[w][oo][4])      = make_float4(p[4], p[5], p[6], p[7]);
            *reinterpret_cast<float4*>(&part[w][oo + 32][0]) = make_float4(q[0], q[1], q[2], q[3]);
            *reinterpret_cast<float4*>(&part[w][oo + 32][4]) = make_float4(q[4], q[5], q[6], q[7]);
        }
        __syncthreads();

        // reduce 8 k-chunks; finalize 2 outputs per thread
        float v0 = xv0, v1 = xv1;
        #pragma unroll
        for (int c = 0; c < 8; c++) {
            float2 pv = *reinterpret_cast<const float2*>(&part[c][ol][b0]);
            v0 += pv.x; v1 += pv.y;
        }
        v0 = fmaxf(v0, 0.f);
        v1 = fmaxf(v1, 0.f);
        float* scn = &g_hsc[(step + 1) & 1][d][0][0];
        __stcg(&scn[(size_t)gb0 * HID + orF], v0);
        __stcg(&scn[(size_t)(gb0 + 1) * HID + orF], v1);

        asm volatile("barrier.cluster.arrive.aligned;" ::: "memory");

        // hidden in the barrier window: hout stores + next-step xp prefetch
        {
            float* ho = hout + ((size_t)s * BATCHN + gb0) * (2 * HID) + d * HID + orF;
            ho[0]       = v0;
            ho[2 * HID] = v1;
        }
        if (step + 1 < SEQL) {
            const int sn = d ? (SEQL - 2 - step) : (step + 1);
            const float* xpb = xp + ((size_t)(d * SEQL + sn) * BATCHN) * HID;
            xv0 = xpb[(size_t)gb0 * HID + orF];
            xv1 = xpb[(size_t)(gb0 + 1) * HID + orF];
        }

        asm volatile("barrier.cluster.wait.aligned;" ::: "memory");
    }
}

// =====================================================================
extern "C" void kernel_launch(void* const* d_in, const int* in_sizes, int n_in,
                              void* d_out, int out_size)
{
    const int*   text   = (const int*)  d_in[0];
    const float* emb    = (const float*)d_in[1];
    const float* emfc_w = (const float*)d_in[2];
    const float* emfc_b = (const float*)d_in[3];
    const float* w_ih0  = (const float*)d_in[4];
    const float* w_hh0  = (const float*)d_in[5];
    const float* b_ih0  = (const float*)d_in[6];
    const float* b_hh0  = (const float*)d_in[7];
    const float* w_ih1  = (const float*)d_in[8];
    const float* w_hh1  = (const float*)d_in[9];
    const float* b_ih1  = (const float*)d_in[10];
    const float* b_hh1  = (const float*)d_in[11];
    const float* fc_w   = (const float*)d_in[12];
    const float* fc_b   = (const float*)d_in[13];
    float* out = (float*)d_out;

    float *p_pe, *p_xp0, *p_h0, *p_xp1, *p_h1;
    cudaGetSymbolAddress((void**)&p_pe,  g_post_emb);
    cudaGetSymbolAddress((void**)&p_xp0, g_xp0);
    cudaGetSymbolAddress((void**)&p_h0,  g_h0);
    cudaGetSymbolAddress((void**)&p_xp1, g_xp1);
    cudaGetSymbolAddress((void**)&p_h1,  g_h1);

    dim3 blk(256);

    // 0) post_emb = gather(emb_table, text) @ emfc_w^T + emfc_b        [16384,256]
    gemm_k<1,0,1,128><<<dim3(EMBD/128, MROWS/128), blk>>>(
        nullptr, emfc_w, emfc_b, nullptr, p_pe, text, emb, EMBD, EMBD, 0, EMBD);

    // 1-2) xp0 split by direction (puts rnn_k at launch index 3 for ncu)
    gemm_k<0,1,2,128><<<dim3(512/128, MROWS/128), blk>>>(
        p_pe, w_ih0, b_ih0, b_hh0, p_xp0, nullptr, nullptr, 512, EMBD, 0, 0);
    gemm_k<0,1,2,128><<<dim3(512/128, MROWS/128), blk>>>(
        p_pe, w_ih0 + (size_t)512 * EMBD, b_ih0, b_hh0, p_xp0,
        nullptr, nullptr, 512, EMBD, 512, 0);

    // 3) layer-0 bidirectional recurrence -> h0 [s][b][1024]
    rnn_k<<<128, blk>>>(p_xp0, w_hh0, p_h0);

    // 4) xp1 = h0 @ w_ih1^T + (b_ih1+b_hh1)                            N=1024,K=1024
    gemm_k<0,1,2,128><<<dim3(1024/128, MROWS/128), blk>>>(
        p_h0, w_ih1, b_ih1, b_hh1, p_xp1, nullptr, nullptr, 1024, 1024, 0, 0);

    // 5) layer-1 recurrence -> h1
    rnn_k<<<128, blk>>>(p_xp1, w_hh1, p_h1);

    // 6) out = h1 @ fc_w^T + fc_b                                      N=18,K=1024
    gemm_k<0,0,1,64><<<dim3(1, MROWS/128), blk>>>(
        p_h1, fc_w, fc_b, nullptr, out, nullptr, nullptr, OUTD, 1024, 0, OUTD);
}